// round 15
// baseline (speedup 1.0000x reference)
#include <cuda_runtime.h>
#include <cuda_fp16.h>
#include <cstdint>

// ---------------- problem dims ----------------
#define NTOK 4096
#define HID  512
#define ROLES 64
#define NCOLS (HID*ROLES)      // 32768
#define HW    (HID/2)          // 256 fp16x2 words per row

// ---------------- tiling ----------------
#define MT 256                 // m rows per block (bigger tile -> half B traffic)
#define NT 128                 // cols per nc chunk
#define KT 64                  // K elems per stage (= 32 words = 128B row)
#define NCHUNK (HID/NT)        // 4
#define KITER (HID/KT)         // 8
#define NSTAGE_TOT (NCHUNK*KITER)  // 32 flat stages
#define NBUF 4

// ---------------- smem (bytes) ----------------
#define SA_BYTES (MT*128)             // 32768 per stage
#define SB_BYTES (NT*128)             // 16384 per stage
#define SM_A   0
#define SM_B   (NBUF*SA_BYTES)        // 131072
#define SM_RED (SM_B + NBUF*SB_BYTES) // 196608
#define SM_TOTAL (SM_RED + MT*4)      // 197632 (1 CTA/SM)

// ---------------- device scratch (static, no runtime alloc) ----------------
__device__ uint32_t g_predH[(size_t)NTOK * HW];    // pred as fp16x2 [n][jw]   (4 MB)
__device__ uint32_t g_UtH[(size_t)NCOLS * HW];     // U^T as fp16x2  [c][jw]   (32 MB)

// ---------------- helpers ----------------
__device__ __forceinline__ uint32_t s2u(const void* p) {
    uint32_t a;
    asm("{ .reg .u64 t; cvta.to.shared.u64 t, %1; cvt.u32.u64 %0, t; }" : "=r"(a) : "l"(p));
    return a;
}
__device__ __forceinline__ void cp16(uint32_t dst_smem, const uint32_t* src) {
    asm volatile("cp.async.cg.shared.global [%0], [%1], 16;"
                 :: "r"(dst_smem), "l"(__cvta_generic_to_global(src)));
}
__device__ __forceinline__ uint32_t pack2(float lo, float hi) {
    __half2 h = __floats2half2_rn(lo, hi);
    return *reinterpret_cast<uint32_t*>(&h);
}

// ---------------- pre-pass 1: pred f32 -> fp16x2 words ----------------
__global__ __launch_bounds__(256)
void pred_cvt_kernel(const float* __restrict__ pred)
{
    size_t i = ((size_t)blockIdx.x * 256 + threadIdx.x) * 4;
    const float4 v = *reinterpret_cast<const float4*>(pred + i);
    uint2 w;
    w.x = pack2(v.x, v.y);
    w.y = pack2(v.z, v.w);
    *reinterpret_cast<uint2*>(g_predH + i / 2) = w;
}

// ---------------- pre-pass 2: U[j][c] -> g_UtH[c][jw] (fp16x2) ----------------
__global__ __launch_bounds__(256)
void transpose_cvt_kernel(const float* __restrict__ U)
{
    __shared__ float t[32][33];
    const int c0 = blockIdx.x * 32;
    const int j0 = blockIdx.y * 32;
    const int tx = threadIdx.x & 31, ty = threadIdx.x >> 5;
    #pragma unroll
    for (int i = 0; i < 4; i++) {
        int j = ty + i * 8;
        t[j][tx] = U[(size_t)(j0 + j) * NCOLS + c0 + tx];
    }
    __syncthreads();
    #pragma unroll
    for (int it = 0; it < 2; it++) {
        int idx = threadIdx.x + it * 256;
        int cc = idx >> 4, jw = idx & 15;
        g_UtH[(size_t)(c0 + cc) * HW + (j0 >> 1) + jw] =
            pack2(t[2 * jw][cc], t[2 * jw + 1][cc]);
    }
}

// ---------------- main kernel: 256 threads (8 warps), 1 CTA/SM ----------------
__global__ __launch_bounds__(256, 1)
void bilinear_main(const float* __restrict__ args,
                   const float* __restrict__ bias1,
                   const float* __restrict__ bias2,
                   float* __restrict__ out)
{
    extern __shared__ char smem[];
    const uint32_t sb = s2u(smem);
    const int tid  = threadIdx.x;
    const int lane = tid & 31, wid = tid >> 5;
    const int warp_m = wid & 3;     // 4 bands of 64 rows (256 total)
    const int warp_n = wid >> 2;    // 2 bands of 64 cols (128 total)
    const int gid = lane >> 2, tig = lane & 3;
    const int m_base = blockIdx.x * MT;
    const int r = blockIdx.y;

    const uint32_t* __restrict__ srcA = g_predH + (size_t)m_base * HW;
    const uint32_t* __restrict__ srcB = g_UtH + (size_t)r * HID * HW;

    // staging coords: 256 threads; rows advance by 32 per iter (row&7 invariant)
    const int sRow = tid >> 3;          // 0..31
    const int sQc  = tid & 7;
    const uint32_t sOff = (uint32_t)sRow * 128 + (((uint32_t)sQc * 16) ^ (((uint32_t)sRow & 7) << 4));
    const size_t  sSrc = (size_t)sRow * HW + sQc * 4;

    // ldmatrix per-lane address components
    const int aRowL = (lane & 7) + ((lane >> 3) & 1) * 8;
    const int aKwL  = (lane >> 4) * 4;
    const int bRowL = (lane & 7) + ((lane >> 4) & 1) * 8;
    const int bKwL  = ((lane >> 3) & 1) * 4;

    float outp[8];
    #pragma unroll
    for (int t = 0; t < 8; t++) outp[t] = 0.f;

    float acc[4][8][4];
    #pragma unroll
    for (int a = 0; a < 4; a++)
        #pragma unroll
        for (int b = 0; b < 8; b++)
            #pragma unroll
            for (int c = 0; c < 4; c++) acc[a][b][c] = 0.f;

    // flat stage s -> (nc = s>>3, kt = s&7); buffer = s%4
    auto issue_stage = [&](int s, int buf) {
        const int kt = s & (KITER - 1);
        const int nc = s >> 3;
        const uint32_t aS = sb + SM_A + buf * SA_BYTES;
        const uint32_t bS = sb + SM_B + buf * SB_BYTES;
        const uint32_t* a0 = srcA + kt * (KT / 2) + sSrc;
        const uint32_t* b0 = srcB + (size_t)(nc * NT) * HW + kt * (KT / 2) + sSrc;
        #pragma unroll
        for (int it = 0; it < 8; it++)     // 8 x 32 rows = 256 A rows
            cp16(aS + sOff + it * 32 * 128, a0 + (size_t)it * 32 * HW);
        #pragma unroll
        for (int it = 0; it < 4; it++)     // 4 x 32 rows = 128 B rows
            cp16(bS + sOff + it * 32 * 128, b0 + (size_t)it * 32 * HW);
    };

    // ---- prologue: 3 stages in flight ----
    issue_stage(0, 0);
    asm volatile("cp.async.commit_group;" ::: "memory");
    issue_stage(1, 1);
    asm volatile("cp.async.commit_group;" ::: "memory");
    issue_stage(2, 2);
    asm volatile("cp.async.commit_group;" ::: "memory");

    int buf = 0, buf3 = 3;
    for (int s = 0; s < NSTAGE_TOT; s++) {
        asm volatile("cp.async.wait_group 2;" ::: "memory");
        __syncthreads();
        if (s + 3 < NSTAGE_TOT) issue_stage(s + 3, buf3);
        asm volatile("cp.async.commit_group;" ::: "memory");

        const uint32_t aBase = sb + SM_A + buf * SA_BYTES;
        const uint32_t bBase = sb + SM_B + buf * SB_BYTES;

        #pragma unroll
        for (int ks = 0; ks < 4; ks++) {
            uint32_t af[4][4];
            #pragma unroll
            for (int wm = 0; wm < 4; wm++) {
                int row = warp_m * 64 + wm * 16 + aRowL;
                int kw  = ks * 8 + aKwL;
                uint32_t addr = aBase + row * 128 + 4 * (kw ^ ((row & 7) << 2));
                asm volatile("ldmatrix.sync.aligned.m8n8.x4.shared.b16 {%0,%1,%2,%3}, [%4];"
                             : "=r"(af[wm][0]), "=r"(af[wm][1]),
                               "=r"(af[wm][2]), "=r"(af[wm][3]) : "r"(addr));
            }
            uint32_t bf[8][2];
            #pragma unroll
            for (int p = 0; p < 4; p++) {
                int row = warp_n * 64 + p * 16 + bRowL;
                int kw  = ks * 8 + bKwL;
                uint32_t addr = bBase + row * 128 + 4 * (kw ^ ((row & 7) << 2));
                asm volatile("ldmatrix.sync.aligned.m8n8.x4.shared.b16 {%0,%1,%2,%3}, [%4];"
                             : "=r"(bf[2 * p][0]), "=r"(bf[2 * p][1]),
                               "=r"(bf[2 * p + 1][0]), "=r"(bf[2 * p + 1][1]) : "r"(addr));
            }
            #pragma unroll
            for (int wn = 0; wn < 8; wn++)
                #pragma unroll
                for (int wm = 0; wm < 4; wm++) {
                    asm volatile(
                        "mma.sync.aligned.m16n8k16.row.col.f32.f16.f16.f32 "
                        "{%0,%1,%2,%3}, {%4,%5,%6,%7}, {%8,%9}, {%0,%1,%2,%3};"
                        : "+f"(acc[wm][wn][0]), "+f"(acc[wm][wn][1]),
                          "+f"(acc[wm][wn][2]), "+f"(acc[wm][wn][3])
                        : "r"(af[wm][0]), "r"(af[wm][1]),
                          "r"(af[wm][2]), "r"(af[wm][3]),
                          "r"(bf[wn][0]), "r"(bf[wn][1]));
                }
        }

        // ---- chunk boundary: fused epilogue (overlaps in-flight cp.async) ----
        if ((s & (KITER - 1)) == (KITER - 1)) {
            const int nc = s >> 3;
            const float* b1p = bias1 + (size_t)r * HID + nc * NT;
            #pragma unroll
            for (int wm = 0; wm < 4; wm++)
                #pragma unroll
                for (int i = 0; i < 2; i++) {
                    int m_loc = warp_m * 64 + wm * 16 + gid + i * 8;
                    const float* arow = args + (size_t)(m_base + m_loc) * HID + nc * NT;
                    float sm = 0.f;
                    #pragma unroll
                    for (int wn = 0; wn < 8; wn++) {
                        int c = warp_n * 64 + wn * 8 + tig * 2;
                        const float2 av = *reinterpret_cast<const float2*>(arow + c);
                        const float2 bv = *reinterpret_cast<const float2*>(b1p + c);
                        sm += (acc[wm][wn][i * 2]     + bv.x) * av.x
                            + (acc[wm][wn][i * 2 + 1] + bv.y) * av.y;
                    }
                    outp[wm * 2 + i] += sm;
                }
            #pragma unroll
            for (int a = 0; a < 4; a++)
                #pragma unroll
                for (int b = 0; b < 8; b++)
                    #pragma unroll
                    for (int c = 0; c < 4; c++) acc[a][b][c] = 0.f;
        }

        buf  = (buf  == NBUF - 1) ? 0 : buf  + 1;
        buf3 = (buf3 == NBUF - 1) ? 0 : buf3 + 1;
    }

    // ---- reduce over tig lanes ----
    #pragma unroll
    for (int t = 0; t < 8; t++) {
        outp[t] += __shfl_xor_sync(0xffffffffu, outp[t], 1);
        outp[t] += __shfl_xor_sync(0xffffffffu, outp[t], 2);
    }

    // ---- cross warp_n reduce via shared, one store per output row ----
    float* sred = reinterpret_cast<float*>(smem + SM_RED);
    sred[tid] = 0.f;
    __syncthreads();
    if (tig == 0) {
        #pragma unroll
        for (int wm = 0; wm < 4; wm++)
            #pragma unroll
            for (int i = 0; i < 2; i++)
                atomicAdd(&sred[warp_m * 64 + wm * 16 + gid + i * 8], outp[wm * 2 + i]);
    }
    __syncthreads();
    out[(size_t)(m_base + tid) * ROLES + r] = sred[tid] + __ldg(&bias2[r]);
}

// ---------------- launch ----------------
extern "C" void kernel_launch(void* const* d_in, const int* in_sizes, int n_in,
                              void* d_out, int out_size) {
    const float* pred  = (const float*)d_in[0];
    const float* args  = (const float*)d_in[1];
    const float* U     = (const float*)d_in[2];
    const float* bias1 = (const float*)d_in[3];
    const float* bias2 = (const float*)d_in[4];
    float* out = (float*)d_out;

    cudaFuncSetAttribute(bilinear_main, cudaFuncAttributeMaxDynamicSharedMemorySize, SM_TOTAL);

    pred_cvt_kernel<<<(NTOK * HID) / (256 * 4), 256>>>(pred);
    transpose_cvt_kernel<<<dim3(NCOLS / 32, HID / 32), 256>>>(U);
    bilinear_main<<<dim3(NTOK / MT, ROLES), 256, SM_TOTAL>>>(args, bias1, bias2, out);
}

// round 17
// speedup vs baseline: 1.1736x; 1.1736x over previous
#include <cuda_runtime.h>
#include <cuda_fp16.h>
#include <cstdint>

// ---------------- problem dims ----------------
#define NTOK 4096
#define HID  512
#define ROLES 64
#define NCOLS (HID*ROLES)      // 32768
#define HW    (HID/2)          // 256 fp16x2 words per row

// ---------------- tiling (R8 proven shape) ----------------
#define MT 128
#define NT 128
#define KT 64                  // 32 words = 128B row per stage
#define NCHUNK (HID/NT)        // 4
#define KITER (HID/KT)         // 8
#define NSTAGE_TOT (NCHUNK*KITER)  // 32
#define NBUF 3
#define TILE_WORDS 4096        // 128 rows x 32 words = 16KB stage tile

// ---------------- smem (bytes) ----------------
#define SA_BYTES (MT*128)           // 16384
#define SB_BYTES (NT*128)           // 16384
#define SM_A   0
#define SM_B   (NBUF*SA_BYTES)      // 49152
#define SM_RED (SM_B + NBUF*SB_BYTES) // 98304
#define SM_TOTAL (SM_RED + MT*4)    // 98816 (2 CTAs/SM)

// ---------------- device scratch (static) ----------------
// stage-tiled, pre-swizzled fp16x2 operand images (smem-ready)
__device__ uint32_t g_predTd[(size_t)NTOK * HW];    // [mblk][kt][tile 4096w]  (4 MB)
__device__ uint32_t g_UtTd[(size_t)NCOLS * HW];     // [r][nc][kt][tile 4096w] (33.5 MB)
__device__ uint32_t g_argsH[(size_t)NTOK * HW];     // args fp16x2 linear [n][jw] (4 MB)

// ---------------- helpers ----------------
__device__ __forceinline__ uint32_t s2u(const void* p) {
    uint32_t a;
    asm("{ .reg .u64 t; cvta.to.shared.u64 t, %1; cvt.u32.u64 %0, t; }" : "=r"(a) : "l"(p));
    return a;
}
__device__ __forceinline__ void cp16(uint32_t dst_smem, const uint32_t* src) {
    asm volatile("cp.async.cg.shared.global [%0], [%1], 16;"
                 :: "r"(dst_smem), "l"(__cvta_generic_to_global(src)));
}
__device__ __forceinline__ uint32_t pack2(float lo, float hi) {
    __half2 h = __floats2half2_rn(lo, hi);
    return *reinterpret_cast<uint32_t*>(&h);
}

// ---------------- pre-pass 1: pred f32 -> tiled/swizzled fp16x2 ----------------
__global__ __launch_bounds__(256)
void pred_cvt_kernel(const float* __restrict__ pred)
{
    size_t p = (size_t)blockIdx.x * 256 + threadIdx.x;   // pair index: 4 floats -> 2 words
    const float4 v = *reinterpret_cast<const float4*>(pred + p * 4);
    uint2 w;
    w.x = pack2(v.x, v.y);
    w.y = pack2(v.z, v.w);
    const int n  = (int)(p >> 7);          // token
    const int w0 = ((int)p & 127) * 2;     // word index within row (even)
    const int mblk = n >> 7, row = n & 127;
    const int kt = w0 >> 5, kw = w0 & 31;
    const uint32_t off = ((uint32_t)(mblk * 8 + kt) * 128 + row) * 32
                       + (kw ^ ((row & 7) << 2));
    *reinterpret_cast<uint2*>(g_predTd + off) = w;
}

// ---------------- pre-pass 1b: args f32 -> fp16x2 linear ----------------
__global__ __launch_bounds__(256)
void args_cvt_kernel(const float* __restrict__ args)
{
    size_t i = ((size_t)blockIdx.x * 256 + threadIdx.x) * 4;
    const float4 v = *reinterpret_cast<const float4*>(args + i);
    uint2 w;
    w.x = pack2(v.x, v.y);
    w.y = pack2(v.z, v.w);
    *reinterpret_cast<uint2*>(g_argsH + i / 2) = w;
}

// ---------------- pre-pass 2: U[j][c] -> tiled/swizzled U^T fp16x2 ----------------
__global__ __launch_bounds__(256)
void transpose_cvt_kernel(const float* __restrict__ U)
{
    __shared__ float t[32][33];
    const int c0 = blockIdx.x * 32;
    const int j0 = blockIdx.y * 32;
    const int tx = threadIdx.x & 31, ty = threadIdx.x >> 5;
    #pragma unroll
    for (int i = 0; i < 4; i++) {
        int j = ty + i * 8;
        t[j][tx] = U[(size_t)(j0 + j) * NCOLS + c0 + tx];
    }
    __syncthreads();
    #pragma unroll
    for (int it = 0; it < 2; it++) {
        int idx = threadIdx.x + it * 256;         // 0..511
        int cc = idx >> 4, jw = idx & 15;         // 32 c x 16 words
        const int c = c0 + cc;
        const int W = (j0 >> 1) + jw;             // global word index 0..255
        const int r = c >> 9, nc = (c >> 7) & 3, row = c & 127;
        const int kt = W >> 5, kw = W & 31;
        const uint32_t off = (((uint32_t)(r * 32 + nc * 8 + kt)) * 128 + row) * 32
                           + (kw ^ ((row & 7) << 2));
        g_UtTd[off] = pack2(t[2 * jw][cc], t[2 * jw + 1][cc]);
    }
}

// ---------------- main kernel: 128 threads (4 warps), 2 CTAs/SM ----------------
__global__ __launch_bounds__(128, 2)
void bilinear_main(const float* __restrict__ bias1,
                   const float* __restrict__ bias2,
                   float* __restrict__ out)
{
    extern __shared__ char smem[];
    const uint32_t sb = s2u(smem);
    const int tid  = threadIdx.x;
    const int lane = tid & 31, wid = tid >> 5;
    const int warp_m = wid & 1;     // 2 bands of 64 rows
    const int warp_n = wid >> 1;    // 2 bands of 64 cols
    const int gid = lane >> 2, tig = lane & 3;
    const int m_base = blockIdx.x * MT;
    const int r = blockIdx.y;

    const uint32_t* __restrict__ srcA = g_predTd + (size_t)blockIdx.x * 8 * TILE_WORDS;
    const uint32_t* __restrict__ srcB = g_UtTd + (size_t)r * 32 * TILE_WORDS;

    // ldmatrix per-lane address components
    const int aRowL = (lane & 7) + ((lane >> 3) & 1) * 8;
    const int aKwL  = (lane >> 4) * 4;
    const int bRowL = (lane & 7) + ((lane >> 4) & 1) * 8;
    const int bKwL  = ((lane >> 3) & 1) * 4;

    float outp[8];
    #pragma unroll
    for (int t = 0; t < 8; t++) outp[t] = 0.f;

    float acc[4][8][4];
    #pragma unroll
    for (int a = 0; a < 4; a++)
        #pragma unroll
        for (int b = 0; b < 8; b++)
            #pragma unroll
            for (int c = 0; c < 4; c++) acc[a][b][c] = 0.f;

    // flat stage s -> A tile (s&7), B tile s; buffer = s%3
    auto issue_stage = [&](int s, int buf) {
        const uint32_t aS = sb + SM_A + buf * SA_BYTES + tid * 16;
        const uint32_t bS = sb + SM_B + buf * SB_BYTES + tid * 16;
        const uint32_t* a0 = srcA + (size_t)(s & (KITER - 1)) * TILE_WORDS + tid * 4;
        const uint32_t* b0 = srcB + (size_t)s * TILE_WORDS + tid * 4;
        #pragma unroll
        for (int it = 0; it < 8; it++)
            cp16(aS + it * 2048, a0 + it * 512);
        #pragma unroll
        for (int it = 0; it < 8; it++)
            cp16(bS + it * 2048, b0 + it * 512);
    };

    issue_stage(0, 0);
    asm volatile("cp.async.commit_group;" ::: "memory");
    issue_stage(1, 1);
    asm volatile("cp.async.commit_group;" ::: "memory");

    int buf = 0, buf2 = 2;
    for (int s = 0; s < NSTAGE_TOT; s++) {
        asm volatile("cp.async.wait_group 1;" ::: "memory");
        __syncthreads();
        if (s + 2 < NSTAGE_TOT) issue_stage(s + 2, buf2);
        asm volatile("cp.async.commit_group;" ::: "memory");

        const uint32_t aBase = sb + SM_A + buf * SA_BYTES;
        const uint32_t bBase = sb + SM_B + buf * SB_BYTES;

        #pragma unroll
        for (int ks = 0; ks < 4; ks++) {
            uint32_t af[4][4];
            #pragma unroll
            for (int wm = 0; wm < 4; wm++) {
                int row = warp_m * 64 + wm * 16 + aRowL;
                int kw  = ks * 8 + aKwL;
                uint32_t addr = aBase + row * 128 + 4 * (kw ^ ((row & 7) << 2));
                asm volatile("ldmatrix.sync.aligned.m8n8.x4.shared.b16 {%0,%1,%2,%3}, [%4];"
                             : "=r"(af[wm][0]), "=r"(af[wm][1]),
                               "=r"(af[wm][2]), "=r"(af[wm][3]) : "r"(addr));
            }
            uint32_t bf[8][2];
            #pragma unroll
            for (int p = 0; p < 4; p++) {
                int row = warp_n * 64 + p * 16 + bRowL;
                int kw  = ks * 8 + bKwL;
                uint32_t addr = bBase + row * 128 + 4 * (kw ^ ((row & 7) << 2));
                asm volatile("ldmatrix.sync.aligned.m8n8.x4.shared.b16 {%0,%1,%2,%3}, [%4];"
                             : "=r"(bf[2 * p][0]), "=r"(bf[2 * p][1]),
                               "=r"(bf[2 * p + 1][0]), "=r"(bf[2 * p + 1][1]) : "r"(addr));
            }
            #pragma unroll
            for (int wn = 0; wn < 8; wn++)
                #pragma unroll
                for (int wm = 0; wm < 4; wm++) {
                    asm volatile(
                        "mma.sync.aligned.m16n8k16.row.col.f32.f16.f16.f32 "
                        "{%0,%1,%2,%3}, {%4,%5,%6,%7}, {%8,%9}, {%0,%1,%2,%3};"
                        : "+f"(acc[wm][wn][0]), "+f"(acc[wm][wn][1]),
                          "+f"(acc[wm][wn][2]), "+f"(acc[wm][wn][3])
                        : "r"(af[wm][0]), "r"(af[wm][1]),
                          "r"(af[wm][2]), "r"(af[wm][3]),
                          "r"(bf[wn][0]), "r"(bf[wn][1]));
                }
        }

        // ---- chunk boundary: fused epilogue (args in fp16) ----
        if ((s & (KITER - 1)) == (KITER - 1)) {
            const int nc = s >> 3;
            const float* b1p = bias1 + (size_t)r * HID + nc * NT;
            #pragma unroll
            for (int wm = 0; wm < 4; wm++)
                #pragma unroll
                for (int i = 0; i < 2; i++) {
                    int m_loc = warp_m * 64 + wm * 16 + gid + i * 8;
                    const uint32_t* arow = g_argsH + (size_t)(m_base + m_loc) * HW + nc * (NT / 2);
                    float sm = 0.f;
                    #pragma unroll
                    for (int wn = 0; wn < 8; wn++) {
                        int c = warp_n * 64 + wn * 8 + tig * 2;
                        const uint32_t aw = __ldg(&arow[c >> 1]);
                        const float2 av = __half22float2(*reinterpret_cast<const __half2*>(&aw));
                        const float2 bv = *reinterpret_cast<const float2*>(b1p + c);
                        sm += (acc[wm][wn][i * 2]     + bv.x) * av.x
                            + (acc[wm][wn][i * 2 + 1] + bv.y) * av.y;
                    }
                    outp[wm * 2 + i] += sm;
                }
            #pragma unroll
            for (int a = 0; a < 4; a++)
                #pragma unroll
                for (int b = 0; b < 8; b++)
                    #pragma unroll
                    for (int c = 0; c < 4; c++) acc[a][b][c] = 0.f;
        }

        buf  = (buf  == 2) ? 0 : buf  + 1;
        buf2 = (buf2 == 2) ? 0 : buf2 + 1;
    }

    // ---- reduce over tig lanes ----
    #pragma unroll
    for (int t = 0; t < 8; t++) {
        outp[t] += __shfl_xor_sync(0xffffffffu, outp[t], 1);
        outp[t] += __shfl_xor_sync(0xffffffffu, outp[t], 2);
    }

    // ---- cross warp_n reduce via shared, one store per output row ----
    float* sred = reinterpret_cast<float*>(smem + SM_RED);
    sred[tid] = 0.f;
    __syncthreads();
    if (tig == 0) {
        #pragma unroll
        for (int wm = 0; wm < 4; wm++)
            #pragma unroll
            for (int i = 0; i < 2; i++)
                atomicAdd(&sred[warp_m * 64 + wm * 16 + gid + i * 8], outp[wm * 2 + i]);
    }
    __syncthreads();
    out[(size_t)(m_base + tid) * ROLES + r] = sred[tid] + __ldg(&bias2[r]);
}

// ---------------- launch ----------------
extern "C" void kernel_launch(void* const* d_in, const int* in_sizes, int n_in,
                              void* d_out, int out_size) {
    const float* pred  = (const float*)d_in[0];
    const float* args  = (const float*)d_in[1];
    const float* U     = (const float*)d_in[2];
    const float* bias1 = (const float*)d_in[3];
    const float* bias2 = (const float*)d_in[4];
    float* out = (float*)d_out;

    cudaFuncSetAttribute(bilinear_main, cudaFuncAttributeMaxDynamicSharedMemorySize, SM_TOTAL);

    pred_cvt_kernel<<<(NTOK * HW) / (256 * 2), 256>>>(pred);
    args_cvt_kernel<<<(NTOK * HID) / (256 * 4), 256>>>(args);
    transpose_cvt_kernel<<<dim3(NCOLS / 32, HID / 32), 256>>>(U);
    bilinear_main<<<dim3(NTOK / MT, ROLES), 128, SM_TOTAL>>>(bias1, bias2, out);
}